// round 3
// baseline (speedup 1.0000x reference)
#include <cuda_runtime.h>
#include <cuda_bf16.h>
#include <cstdint>

// ---------------------------------------------------------------------------
// Problem constants
// ---------------------------------------------------------------------------
#define T_STEPS   1024
#define BATCH     64
#define N_IN      256
#define N_HID     512
#define M_TOTAL   (T_STEPS * BATCH)       // 65536
#define YN        (BATCH * N_HID)         // 32768

#define GAIN_REC  0.04419417382415922f    // 1/sqrt(512)
#define DT_H      0.1f

// ---------------------------------------------------------------------------
// Scratch (device global; no dynamic allocation allowed)
// ---------------------------------------------------------------------------
__device__ float g_ext[(size_t)M_TOTAL * N_HID];   // 134 MB: inputs @ W_ih + b_ih

// ---------------------------------------------------------------------------
// Kernel A: ext = inputs @ W_ih + b_ih   (M=65536, N=512, K=256) fp32 tiled
// (unchanged from round 2 — known-good, ~480us; optimize next round)
// ---------------------------------------------------------------------------
#define TA_M 64
#define TA_N 64
#define TA_K 32

__global__ __launch_bounds__(256) void ext_gemm_kernel(
    const float* __restrict__ A,     // [M_TOTAL, 256]
    const float* __restrict__ W,     // [256, 512]
    const float* __restrict__ bias)  // [512]
{
    __shared__ float As[TA_K][TA_M + 4];
    __shared__ float Bs[TA_K][TA_N];

    const int tid = threadIdx.x;
    const int tx  = tid & 15;
    const int ty  = tid >> 4;
    const int m0  = blockIdx.y * TA_M;
    const int n0  = blockIdx.x * TA_N;

    float acc[4][4];
#pragma unroll
    for (int i = 0; i < 4; ++i)
#pragma unroll
        for (int j = 0; j < 4; ++j) acc[i][j] = 0.f;

    for (int kt = 0; kt < N_IN; kt += TA_K) {
#pragma unroll
        for (int j = 0; j < 2; ++j) {
            int f  = tid + j * 256;
            int r  = f >> 3;
            int c4 = f & 7;
            float4 v = *(const float4*)&A[(size_t)(m0 + r) * N_IN + kt + c4 * 4];
            As[c4 * 4 + 0][r] = v.x;
            As[c4 * 4 + 1][r] = v.y;
            As[c4 * 4 + 2][r] = v.z;
            As[c4 * 4 + 3][r] = v.w;
        }
#pragma unroll
        for (int j = 0; j < 2; ++j) {
            int f  = tid + j * 256;
            int r  = f >> 4;
            int c4 = f & 15;
            *(float4*)&Bs[r][c4 * 4] =
                *(const float4*)&W[(size_t)(kt + r) * N_HID + n0 + c4 * 4];
        }
        __syncthreads();

#pragma unroll
        for (int k = 0; k < TA_K; ++k) {
            float a[4], bb[4];
            *(float4*)a  = *(const float4*)&As[k][ty * 4];
            *(float4*)bb = *(const float4*)&Bs[k][tx * 4];
#pragma unroll
            for (int i = 0; i < 4; ++i)
#pragma unroll
                for (int j = 0; j < 4; ++j)
                    acc[i][j] = fmaf(a[i], bb[j], acc[i][j]);
        }
        __syncthreads();
    }

    float4 bv = *(const float4*)&bias[n0 + tx * 4];
#pragma unroll
    for (int i = 0; i < 4; ++i) {
        int m = m0 + ty * 4 + i;
        float4 o;
        o.x = acc[i][0] + bv.x;
        o.y = acc[i][1] + bv.y;
        o.z = acc[i][2] + bv.z;
        o.w = acc[i][3] + bv.w;
        *(float4*)&g_ext[(size_t)m * N_HID + n0 + tx * 4] = o;
    }
}

// ---------------------------------------------------------------------------
// Kernel B: persistent recurrence, 16 clusters x 8 CTAs.
//   Cluster = 4 batch rows x all 512 hidden. CTA = 4b x 64h (rank picks h0).
//   y state lives entirely in cluster SMEM: each CTA DSMEM-broadcasts its
//   256 yn values to all 8 peers each step; barrier.cluster syncs the step.
//   Dot uses fma.rn.f32x2 with k split over 2 thread halves + SMEM reduce.
// ---------------------------------------------------------------------------
#define RNT 512

// SMEM layout (floats)
#define WS_F   0                      // W slice: 512k x 64h as [k4][hl] float4 = 32768 floats
#define YS_F   32768                  // y tiles: 2 buffers x 4 rows x 516 floats (129 f4/row)
#define YS_BUF 2064                   // floats per ys buffer
#define RED_F  (YS_F + 2 * YS_BUF)    // 36896: k-split partial sums (256 floats)
#define YNB_F  (RED_F + 256)          // 37152: yn staging, 4 rows stride 72 (288 floats)
#define SMEM_R_BYTES ((YNB_F + 288) * 4)   // 149760 bytes

__global__ void __cluster_dims__(8, 1, 1) __launch_bounds__(RNT, 1)
horn_rec2(const float* __restrict__ W_hh,
          const float* __restrict__ b_hh,
          const float* __restrict__ alpha,
          const float* __restrict__ omega,
          const float* __restrict__ gamma,
          const float* __restrict__ vvec,
          float* __restrict__ out)
{
    extern __shared__ float smem[];

    const int tid  = threadIdx.x;
    const int bg   = blockIdx.x >> 3;     // cluster id: batch rows bg*4..+4
    const int rank = blockIdx.x & 7;      // CTA rank in cluster: h0 = rank*64
    const int h0   = rank * 64;
    const int kh   = tid >> 8;            // k-half (0: k<256, 1: k>=256)
    const int wid8 = (tid >> 5) & 7;
    const int lane = tid & 31;
    const int bl   = lane >> 3;           // local batch row 0..3
    const int hl   = wid8 * 8 + (lane & 7); // local hidden 0..63
    const int b    = bg * 4 + bl;
    const int h    = h0 + hl;

    // ---- fill W slice: ws[k4*64 + hl] float4 packs k-quad ----
    for (int idx = tid; idx < 64 * N_HID; idx += RNT) {
        int k = idx >> 6;
        int l = idx & 63;
        smem[WS_F + (k >> 2) * 256 + l * 4 + (k & 3)] =
            W_hh[(size_t)k * N_HID + h0 + l];
    }

    // ---- per-thread parameters ----
    const float bhh = __ldg(&b_hh[h]);
    const float al  = __ldg(&alpha[h]);
    const float om  = __ldg(&omega[h]);
    const float om2 = om * om;
    const float g2  = 2.f * __ldg(&gamma[h]);
    const float vv  = __ldg(&vvec[h]);

    float x = 0.f, y = 0.f;
    const float* extp = g_ext + (size_t)b * N_HID + h;
    float*       outp = out   + (size_t)b * N_HID + h;
    const uint32_t smem_u32 = (uint32_t)__cvta_generic_to_shared(smem);

    float e_cur = 0.f;
    if (kh == 0) e_cur = __ldcg((float*)extp);     // ext for t=0

    __syncthreads();                                // ws ready

    // W pointer for this thread's k-half / hidden column (16B entries)
    const ulonglong2* wsp = ((const ulonglong2*)smem) + kh * 64 * 64 + hl;

    for (int t = 0; t < T_STEPS; ++t) {
        // prefetch ext for next step (full step of latency to hide)
        float e_nxt = 0.f;
        if (kh == 0)
            e_nxt = __ldcg((float*)(extp + (size_t)((t + 1) & (T_STEPS - 1)) * YN));

        // ---- half-dot over this thread's 256 k values ----
        float part = 0.f;
        if (t > 0) {
            const ulonglong2* yp = ((const ulonglong2*)(smem + YS_F))
                                 + (t & 1) * 516 + bl * 129 + kh * 64;
            unsigned long long a0 = 0ull, a1 = 0ull;   // f32x2 accumulators
#pragma unroll 16
            for (int j = 0; j < 64; ++j) {
                ulonglong2 yv = yp[j];
                ulonglong2 wv = wsp[j * 64];
                asm("fma.rn.f32x2 %0, %1, %2, %0;" : "+l"(a0) : "l"(yv.x), "l"(wv.x));
                asm("fma.rn.f32x2 %0, %1, %2, %0;" : "+l"(a1) : "l"(yv.y), "l"(wv.y));
            }
            float2 f0 = *(float2*)&a0;
            float2 f1 = *(float2*)&a1;
            part = (f0.x + f0.y) + (f1.x + f1.y);
        }

        if (kh == 1) smem[RED_F + (tid & 255)] = part;
        __syncthreads();

        if (kh == 0) {
            float acc = part + smem[RED_F + tid];
            // ---- HORN dynamics ----
            float inp = e_cur + GAIN_REC * (acc + bhh + vv * x);
            float yn  = fmaf(DT_H, al * tanhf(inp) - om2 * x - g2 * y, y);
            float xn  = fmaf(DT_H, yn, x);
            x = xn; y = yn;
            smem[YNB_F + bl * 72 + hl] = yn;          // stage for broadcast
            outp[(size_t)t * YN] = xn;
            e_cur = e_nxt;
        }
        __syncthreads();                              // ynbuf ready

        // ---- DSMEM broadcast: 512 threads push 64 float4 to 8 ranks ----
        {
            int r   = tid >> 6;                       // target rank 0..7
            int c   = tid & 63;                       // float4 index 0..63
            int cbl = c >> 4;
            int cq  = c & 15;
            const uint4 val = *(const uint4*)&smem[YNB_F + cbl * 72 + cq * 4];
            uint32_t dstLocal = smem_u32
                + (uint32_t)((YS_F + ((t + 1) & 1) * YS_BUF) * 4
                             + (cbl * 129 + rank * 16 + cq) * 16);
            uint32_t remote;
            asm("mapa.shared::cluster.u32 %0, %1, %2;"
                : "=r"(remote) : "r"(dstLocal), "r"(r));
            asm volatile("st.shared::cluster.v4.b32 [%0], {%1, %2, %3, %4};"
                         :: "r"(remote), "r"(val.x), "r"(val.y),
                            "r"(val.z), "r"(val.w) : "memory");
        }

        // ---- cluster barrier: orders DSMEM stores for next step ----
        asm volatile("barrier.cluster.arrive.aligned;" ::: "memory");
        asm volatile("barrier.cluster.wait.aligned;"   ::: "memory");
    }
}

// ---------------------------------------------------------------------------
// Launch
// ---------------------------------------------------------------------------
extern "C" void kernel_launch(void* const* d_in, const int* in_sizes, int n_in,
                              void* d_out, int out_size)
{
    const float* inputs = (const float*)d_in[0];   // [1024,64,256]
    const float* W_ih   = (const float*)d_in[1];   // [256,512]
    const float* b_ih   = (const float*)d_in[2];   // [512]
    const float* W_hh   = (const float*)d_in[3];   // [512,512]
    const float* b_hh   = (const float*)d_in[4];   // [512]
    const float* alpha  = (const float*)d_in[5];   // [512]
    const float* omega  = (const float*)d_in[6];   // [512]
    const float* gamma  = (const float*)d_in[7];   // [512]
    const float* v      = (const float*)d_in[8];   // [512]
    float* out = (float*)d_out;                    // [1024,64,512]

    (void)in_sizes; (void)n_in; (void)out_size;

    cudaFuncSetAttribute(horn_rec2,
                         cudaFuncAttributeMaxDynamicSharedMemorySize,
                         SMEM_R_BYTES);

    dim3 gA(N_HID / TA_N, M_TOTAL / TA_M);         // (8, 1024)
    ext_gemm_kernel<<<gA, 256>>>(inputs, W_ih, b_ih);

    horn_rec2<<<128, RNT, SMEM_R_BYTES>>>(W_hh, b_hh, alpha, omega,
                                          gamma, v, out);
}

// round 4
// speedup vs baseline: 1.4188x; 1.4188x over previous
#include <cuda_runtime.h>
#include <cuda_bf16.h>
#include <cstdint>

// ---------------------------------------------------------------------------
// Problem constants
// ---------------------------------------------------------------------------
#define T_STEPS   1024
#define BATCH     64
#define N_IN      256
#define N_HID     512
#define M_TOTAL   (T_STEPS * BATCH)       // 65536
#define YN        (BATCH * N_HID)         // 32768

#define GAIN_REC  0.04419417382415922f    // 1/sqrt(512)
#define DT_H      0.1f

__device__ float g_ext[(size_t)M_TOTAL * N_HID];   // inputs @ W_ih + b_ih

// ---------------------------------------------------------------------------
// Kernel A: ext = inputs @ W_ih + b_ih   (unchanged; ~0.45ms)
// ---------------------------------------------------------------------------
#define TA_M 64
#define TA_N 64
#define TA_K 32

__global__ __launch_bounds__(256) void ext_gemm_kernel(
    const float* __restrict__ A, const float* __restrict__ W,
    const float* __restrict__ bias)
{
    __shared__ float As[TA_K][TA_M + 4];
    __shared__ float Bs[TA_K][TA_N];

    const int tid = threadIdx.x;
    const int tx  = tid & 15;
    const int ty  = tid >> 4;
    const int m0  = blockIdx.y * TA_M;
    const int n0  = blockIdx.x * TA_N;

    float acc[4][4];
#pragma unroll
    for (int i = 0; i < 4; ++i)
#pragma unroll
        for (int j = 0; j < 4; ++j) acc[i][j] = 0.f;

    for (int kt = 0; kt < N_IN; kt += TA_K) {
#pragma unroll
        for (int j = 0; j < 2; ++j) {
            int f  = tid + j * 256;
            int r  = f >> 3;
            int c4 = f & 7;
            float4 v = *(const float4*)&A[(size_t)(m0 + r) * N_IN + kt + c4 * 4];
            As[c4 * 4 + 0][r] = v.x;
            As[c4 * 4 + 1][r] = v.y;
            As[c4 * 4 + 2][r] = v.z;
            As[c4 * 4 + 3][r] = v.w;
        }
#pragma unroll
        for (int j = 0; j < 2; ++j) {
            int f  = tid + j * 256;
            int r  = f >> 4;
            int c4 = f & 15;
            *(float4*)&Bs[r][c4 * 4] =
                *(const float4*)&W[(size_t)(kt + r) * N_HID + n0 + c4 * 4];
        }
        __syncthreads();
#pragma unroll
        for (int k = 0; k < TA_K; ++k) {
            float a[4], bb[4];
            *(float4*)a  = *(const float4*)&As[k][ty * 4];
            *(float4*)bb = *(const float4*)&Bs[k][tx * 4];
#pragma unroll
            for (int i = 0; i < 4; ++i)
#pragma unroll
                for (int j = 0; j < 4; ++j)
                    acc[i][j] = fmaf(a[i], bb[j], acc[i][j]);
        }
        __syncthreads();
    }

    float4 bv = *(const float4*)&bias[n0 + tx * 4];
#pragma unroll
    for (int i = 0; i < 4; ++i) {
        int m = m0 + ty * 4 + i;
        float4 o;
        o.x = acc[i][0] + bv.x;
        o.y = acc[i][1] + bv.y;
        o.z = acc[i][2] + bv.z;
        o.w = acc[i][3] + bv.w;
        *(float4*)&g_ext[(size_t)m * N_HID + n0 + tx * 4] = o;
    }
}

// ---------------------------------------------------------------------------
// Kernel B: persistent recurrence, 16 clusters x 8 CTAs.
//   Cluster owns 4 batch rows, split into 2 pipelined groups (A: rows 0-1,
//   B: rows 2-3). Half-steps alternate A/B so mbarrier sync latency is hidden
//   behind the other group's compute. DSMEM drain+arrive confined to warp 15.
// ---------------------------------------------------------------------------
#define RNT 512

// SMEM layout (float indices)
#define WS_F    0                     // W slice [k4][hl] float4: 32768 floats
#define YS_F    32768                 // 4 bufs (G,p) x [bl(2)][512]: 4096 f
#define RED_F   36864                 // partials [kh(8)][bl(2)][hl(64)]: 1024 f
#define STAG_F  37888                 // yn staging [bl*64+hl]: 128 f
#define MBAR_F  38016                 // 2 mbarriers (16 B)
#define SMEM_R_BYTES ((38016 + 8) * 4)

__device__ __forceinline__ void mbar_init(uint32_t a, uint32_t cnt) {
    asm volatile("mbarrier.init.shared.b64 [%0], %1;" :: "r"(a), "r"(cnt) : "memory");
}
__device__ __forceinline__ void mbar_arrive_cluster(uint32_t a, uint32_t rank) {
    asm volatile("{\n\t.reg .b32 ra;\n\t"
                 "mapa.shared::cluster.u32 ra, %0, %1;\n\t"
                 "mbarrier.arrive.release.cluster.shared::cluster.b64 _, [ra];\n\t}"
                 :: "r"(a), "r"(rank) : "memory");
}
__device__ __forceinline__ void mbar_wait_parity(uint32_t a, uint32_t par) {
    asm volatile("{\n\t.reg .pred P;\n\t"
                 "WL_%=:\n\t"
                 "mbarrier.try_wait.parity.acquire.cluster.shared::cta.b64 P, [%0], %1, 0x989680;\n\t"
                 "@P bra WD_%=;\n\t"
                 "bra WL_%=;\n\t"
                 "WD_%=:\n\t}"
                 :: "r"(a), "r"(par) : "memory");
}

__global__ void __cluster_dims__(8, 1, 1) __launch_bounds__(RNT, 1)
horn_rec3(const float* __restrict__ W_hh,
          const float* __restrict__ b_hh,
          const float* __restrict__ alpha,
          const float* __restrict__ omega,
          const float* __restrict__ gamma,
          const float* __restrict__ vvec,
          float* __restrict__ out)
{
    extern __shared__ float smem[];

    const int tid  = threadIdx.x;
    const int bg   = blockIdx.x >> 3;           // cluster id (16)
    const int rank = blockIdx.x & 7;            // h0 = rank*64
    const int h0   = rank * 64;
    const int kh   = tid >> 6;                  // k-slice 0..7 (64 k each)
    const int hl   = tid & 63;                  // hidden column 0..63
    const uint32_t smem_u32 = (uint32_t)__cvta_generic_to_shared(smem);
    const uint32_t mbarA = smem_u32 + MBAR_F * 4;
    const uint32_t mbarB = mbarA + 8;

    // ---- fill W slice: ws[k4*64 + hl_col] float4 packs a k-quad ----
    for (int idx = tid; idx < 64 * N_HID; idx += RNT) {
        int k = idx >> 6;
        int l = idx & 63;
        smem[WS_F + (k >> 2) * 256 + l * 4 + (k & 3)] =
            W_hh[(size_t)k * N_HID + h0 + l];
    }

    if (tid == 0) {
        mbar_init(mbarA, 8);
        mbar_init(mbarB, 8);
    }
    __syncthreads();
    asm volatile("barrier.cluster.arrive.aligned;" ::: "memory");
    asm volatile("barrier.cluster.wait.aligned;"   ::: "memory");

    // ---- dynamics-thread state (tid < 128: bl = tid>>6, hl = tid&63) ----
    const int dbl = tid >> 6;                   // valid when tid < 128
    const int dh  = h0 + (tid & 63);
    float bhh = 0.f, al = 0.f, om2 = 0.f, g2 = 0.f, vv = 0.f;
    float xs[2] = {0.f, 0.f}, ys[2] = {0.f, 0.f};
    float ec[2] = {0.f, 0.f}, en[2] = {0.f, 0.f};
    const float* ep[2] = {nullptr, nullptr};
    float*       op[2] = {nullptr, nullptr};
    if (tid < 128) {
        bhh = __ldg(&b_hh[dh]);
        al  = __ldg(&alpha[dh]);
        float om = __ldg(&omega[dh]);
        om2 = om * om;
        g2  = 2.f * __ldg(&gamma[dh]);
        vv  = __ldg(&vvec[dh]);
#pragma unroll
        for (int G = 0; G < 2; ++G) {
            int b = bg * 4 + G * 2 + dbl;
            ep[G] = g_ext + (size_t)b * N_HID + dh;
            op[G] = out   + (size_t)b * N_HID + dh;
            ec[G] = __ldcg((float*)ep[G]);      // ext for t=0
        }
    }

    // dot-phase pointers (all 512 threads)
    const ulonglong2* wp = ((const ulonglong2*)smem) + (kh * 16) * 64 + hl;

    const int warp = tid >> 5;
    const int lane = tid & 31;

    for (int t = 0; t < T_STEPS; ++t) {
#pragma unroll
        for (int G = 0; G < 2; ++G) {
            const uint32_t mbar = (G == 0) ? mbarA : mbarB;

            // ---- wait for all 8 ranks' y_{t-1} broadcasts (hidden) ----
            if (t > 0) {
                mbar_wait_parity(mbar, (unsigned)((t - 1) & 1));

                // ---- dot over this thread's 64-k slice, both rows ----
                const ulonglong2* y0p = ((const ulonglong2*)
                    (smem + YS_F + (G * 2 + ((t - 1) & 1)) * 1024)) + kh * 16;
                const ulonglong2* y1p = y0p + 128;
                unsigned long long a00 = 0ull, a01 = 0ull, a10 = 0ull, a11 = 0ull;
#pragma unroll
                for (int j = 0; j < 16; ++j) {
                    ulonglong2 wv = wp[j * 64];
                    ulonglong2 v0 = y0p[j];
                    ulonglong2 v1 = y1p[j];
                    asm("fma.rn.f32x2 %0, %1, %2, %0;" : "+l"(a00) : "l"(v0.x), "l"(wv.x));
                    asm("fma.rn.f32x2 %0, %1, %2, %0;" : "+l"(a01) : "l"(v0.y), "l"(wv.y));
                    asm("fma.rn.f32x2 %0, %1, %2, %0;" : "+l"(a10) : "l"(v1.x), "l"(wv.x));
                    asm("fma.rn.f32x2 %0, %1, %2, %0;" : "+l"(a11) : "l"(v1.y), "l"(wv.y));
                }
                float2 f00 = *(float2*)&a00, f01 = *(float2*)&a01;
                float2 f10 = *(float2*)&a10, f11 = *(float2*)&a11;
                smem[RED_F + kh * 128 +      hl] = (f00.x + f00.y) + (f01.x + f01.y);
                smem[RED_F + kh * 128 + 64 + hl] = (f10.x + f10.y) + (f11.x + f11.y);
            }
            __syncthreads();

            // ---- dynamics (warps 0-3) ----
            if (tid < 128) {
                float acc = 0.f;
                if (t > 0) {
#pragma unroll
                    for (int k = 0; k < 8; ++k)
                        acc += smem[RED_F + k * 128 + tid];
                }
                float inp = ec[G] + GAIN_REC * (acc + bhh + vv * xs[G]);
                float yn  = fmaf(DT_H, al * tanhf(inp) - om2 * xs[G] - g2 * ys[G], ys[G]);
                float xn  = fmaf(DT_H, yn, xs[G]);
                xs[G] = xn; ys[G] = yn;
                smem[STAG_F + tid] = yn;
                op[G][(size_t)t * YN] = xn;
                en[G] = __ldcg((float*)(ep[G] + (size_t)((t + 1) & (T_STEPS - 1)) * YN));
                ec[G] = en[G];
            }
            __syncthreads();

            // ---- broadcast yn to all 8 ranks (warps 8-15) ----
            if (warp >= 8) {
                int i  = tid - 256;              // 0..255
                int r  = i >> 5;                 // target rank
                int j  = i & 31;                 // float4 idx (32 = 128 floats)
                int jb = j >> 4;                 // bl
                int jq = j & 15;                 // quad within 64
                uint4 val = *(const uint4*)&smem[STAG_F + jb * 64 + jq * 4];
                uint32_t dstLocal = smem_u32 +
                    (uint32_t)((YS_F + (G * 2 + (t & 1)) * 1024
                                + jb * 512 + rank * 64 + jq * 4) * 4);
                uint32_t remote;
                asm("mapa.shared::cluster.u32 %0, %1, %2;"
                    : "=r"(remote) : "r"(dstLocal), "r"(r));
                asm volatile("st.shared::cluster.v4.b32 [%0], {%1, %2, %3, %4};"
                             :: "r"(remote), "r"(val.x), "r"(val.y),
                                "r"(val.z), "r"(val.w) : "memory");
                if (warp == 15) {
                    // straggler warp: wait drain, fence, arrive on all ranks
                    asm volatile("bar.sync 1, 256;" ::: "memory");
                    asm volatile("fence.acq_rel.cluster;" ::: "memory");
                    if (lane < 8) mbar_arrive_cluster(mbar, (uint32_t)lane);
                } else {
                    asm volatile("bar.arrive 1, 256;" ::: "memory");
                }
            }
            // warps 0-7 proceed straight to the other group's half-step
        }
    }

    asm volatile("barrier.cluster.arrive.aligned;" ::: "memory");
    asm volatile("barrier.cluster.wait.aligned;"   ::: "memory");
}

// ---------------------------------------------------------------------------
// Launch
// ---------------------------------------------------------------------------
extern "C" void kernel_launch(void* const* d_in, const int* in_sizes, int n_in,
                              void* d_out, int out_size)
{
    const float* inputs = (const float*)d_in[0];
    const float* W_ih   = (const float*)d_in[1];
    const float* b_ih   = (const float*)d_in[2];
    const float* W_hh   = (const float*)d_in[3];
    const float* b_hh   = (const float*)d_in[4];
    const float* alpha  = (const float*)d_in[5];
    const float* omega  = (const float*)d_in[6];
    const float* gamma  = (const float*)d_in[7];
    const float* v      = (const float*)d_in[8];
    float* out = (float*)d_out;

    (void)in_sizes; (void)n_in; (void)out_size;

    cudaFuncSetAttribute(horn_rec3,
                         cudaFuncAttributeMaxDynamicSharedMemorySize,
                         SMEM_R_BYTES);

    dim3 gA(N_HID / TA_N, M_TOTAL / TA_M);
    ext_gemm_kernel<<<gA, 256>>>(inputs, W_ih, b_ih);

    horn_rec3<<<128, RNT, SMEM_R_BYTES>>>(W_hh, b_hh, alpha, omega,
                                          gamma, v, out);
}

// round 5
// speedup vs baseline: 1.6211x; 1.1426x over previous
#include <cuda_runtime.h>
#include <cuda_bf16.h>
#include <cstdint>

// ---------------------------------------------------------------------------
// Problem constants
// ---------------------------------------------------------------------------
#define T_STEPS   1024
#define BATCH     64
#define N_IN      256
#define N_HID     512
#define M_TOTAL   (T_STEPS * BATCH)       // 65536
#define YN        (BATCH * N_HID)         // 32768

#define GAIN_REC  0.04419417382415922f    // 1/sqrt(512)
#define DT_H      0.1f

__device__ float g_ext[(size_t)M_TOTAL * N_HID];   // inputs @ W_ih + b_ih

// ---------------------------------------------------------------------------
// Kernel A: ext = inputs @ W_ih + b_ih   (unchanged; ~0.45ms)
// ---------------------------------------------------------------------------
#define TA_M 64
#define TA_N 64
#define TA_K 32

__global__ __launch_bounds__(256) void ext_gemm_kernel(
    const float* __restrict__ A, const float* __restrict__ W,
    const float* __restrict__ bias)
{
    __shared__ float As[TA_K][TA_M + 4];
    __shared__ float Bs[TA_K][TA_N];

    const int tid = threadIdx.x;
    const int tx  = tid & 15;
    const int ty  = tid >> 4;
    const int m0  = blockIdx.y * TA_M;
    const int n0  = blockIdx.x * TA_N;

    float acc[4][4];
#pragma unroll
    for (int i = 0; i < 4; ++i)
#pragma unroll
        for (int j = 0; j < 4; ++j) acc[i][j] = 0.f;

    for (int kt = 0; kt < N_IN; kt += TA_K) {
#pragma unroll
        for (int j = 0; j < 2; ++j) {
            int f  = tid + j * 256;
            int r  = f >> 3;
            int c4 = f & 7;
            float4 v = *(const float4*)&A[(size_t)(m0 + r) * N_IN + kt + c4 * 4];
            As[c4 * 4 + 0][r] = v.x;
            As[c4 * 4 + 1][r] = v.y;
            As[c4 * 4 + 2][r] = v.z;
            As[c4 * 4 + 3][r] = v.w;
        }
#pragma unroll
        for (int j = 0; j < 2; ++j) {
            int f  = tid + j * 256;
            int r  = f >> 4;
            int c4 = f & 15;
            *(float4*)&Bs[r][c4 * 4] =
                *(const float4*)&W[(size_t)(kt + r) * N_HID + n0 + c4 * 4];
        }
        __syncthreads();
#pragma unroll
        for (int k = 0; k < TA_K; ++k) {
            float a[4], bb[4];
            *(float4*)a  = *(const float4*)&As[k][ty * 4];
            *(float4*)bb = *(const float4*)&Bs[k][tx * 4];
#pragma unroll
            for (int i = 0; i < 4; ++i)
#pragma unroll
                for (int j = 0; j < 4; ++j)
                    acc[i][j] = fmaf(a[i], bb[j], acc[i][j]);
        }
        __syncthreads();
    }

    float4 bv = *(const float4*)&bias[n0 + tx * 4];
#pragma unroll
    for (int i = 0; i < 4; ++i) {
        int m = m0 + ty * 4 + i;
        float4 o;
        o.x = acc[i][0] + bv.x;
        o.y = acc[i][1] + bv.y;
        o.z = acc[i][2] + bv.z;
        o.w = acc[i][3] + bv.w;
        *(float4*)&g_ext[(size_t)m * N_HID + n0 + tx * 4] = o;
    }
}

// ---------------------------------------------------------------------------
// Kernel B: persistent recurrence, 16 clusters x 8 CTAs.
//   Cluster = 4 batch rows x 512 hidden; CTA rank owns 64 h-columns.
//   Per step: mbar-wait -> dot (all 4 rows, W read once) -> dynamics ->
//   st.async yn broadcast (tx-counting mbarrier; no fences, no barriers).
// ---------------------------------------------------------------------------
#define RNT 512

// SMEM layout (float indices)
#define WS_F    0                      // W slice [k4][hl] float4: 32768 floats
#define YS_F    32768                  // 2 bufs x [row(4)][512 f]: 4096 floats
#define RED_F   36864                  // partials [kh(8)][row(4)][hl(64)]: 2048
#define STAG_F  38912                  // yn staging [row*64+hl]: 256 floats
#define MBAR_F  39168                  // 2 mbarriers (16 B)
#define SMEM_R_BYTES ((MBAR_F + 4) * 4)

#define TX_BYTES 8192u                 // 8 ranks x 4 rows x 64 h x 4 B

__device__ __forceinline__ void mbar_init(uint32_t a, uint32_t cnt) {
    asm volatile("mbarrier.init.shared.b64 [%0], %1;" :: "r"(a), "r"(cnt) : "memory");
}
__device__ __forceinline__ void mbar_expect_tx(uint32_t a, uint32_t bytes) {
    asm volatile("mbarrier.arrive.expect_tx.shared.b64 _, [%0], %1;"
                 :: "r"(a), "r"(bytes) : "memory");
}
__device__ __forceinline__ void mbar_wait_parity(uint32_t a, uint32_t par) {
    asm volatile("{\n\t.reg .pred P;\n\t"
                 "WL_%=:\n\t"
                 "mbarrier.try_wait.parity.acquire.cluster.shared::cta.b64 P, [%0], %1, 0x989680;\n\t"
                 "@P bra WD_%=;\n\t"
                 "bra WL_%=;\n\t"
                 "WD_%=:\n\t}"
                 :: "r"(a), "r"(par) : "memory");
}
// st.async 16B to remote rank's smem, tx-completing on that rank's mbarrier
__device__ __forceinline__ void st_async_v4(uint32_t dstLocal, uint32_t mbarLocal,
                                            uint32_t rank, uint4 v) {
    asm volatile("{\n\t.reg .b32 rd, rm;\n\t"
                 "mapa.shared::cluster.u32 rd, %0, %2;\n\t"
                 "mapa.shared::cluster.u32 rm, %1, %2;\n\t"
                 "st.async.shared::cluster.mbarrier::complete_tx::bytes.v4.b32 "
                 "[rd], {%3, %4, %5, %6}, [rm];\n\t}"
                 :: "r"(dstLocal), "r"(mbarLocal), "r"(rank),
                    "r"(v.x), "r"(v.y), "r"(v.z), "r"(v.w) : "memory");
}

__global__ void __cluster_dims__(8, 1, 1) __launch_bounds__(RNT, 1)
horn_rec4(const float* __restrict__ W_hh,
          const float* __restrict__ b_hh,
          const float* __restrict__ alpha,
          const float* __restrict__ omega,
          const float* __restrict__ gamma,
          const float* __restrict__ vvec,
          float* __restrict__ out)
{
    extern __shared__ float smem[];

    const int tid  = threadIdx.x;
    const int bg   = blockIdx.x >> 3;           // cluster id (16)
    const int rank = blockIdx.x & 7;            // h0 = rank*64
    const int h0   = rank * 64;
    const int kh   = tid >> 6;                  // k-slice 0..7 (64 k each)
    const int hl   = tid & 63;                  // hidden column 0..63
    const uint32_t smem_u32 = (uint32_t)__cvta_generic_to_shared(smem);
    const uint32_t mbar0 = smem_u32 + MBAR_F * 4;
    const uint32_t mbar1 = mbar0 + 8;

    // ---- fill W slice: ws[k4*64 + col] float4 packs a k-quad ----
    for (int idx = tid; idx < 64 * N_HID; idx += RNT) {
        int k = idx >> 6;
        int l = idx & 63;
        smem[WS_F + (k >> 2) * 256 + l * 4 + (k & 3)] =
            W_hh[(size_t)k * N_HID + h0 + l];
    }

    if (tid == 0) {
        mbar_init(mbar0, 1);
        mbar_init(mbar1, 1);
        mbar_expect_tx(mbar0, TX_BYTES);        // arm for y_0 (step 0 bcast)
        mbar_expect_tx(mbar1, TX_BYTES);        // arm for y_1 (step 1 bcast)
    }
    __syncthreads();
    asm volatile("barrier.cluster.arrive.aligned;" ::: "memory");
    asm volatile("barrier.cluster.wait.aligned;"   ::: "memory");

    // ---- dynamics-thread state (tid < 256: row = tid>>6, h = h0 + tid&63) ----
    const int dh = h0 + (tid & 63);
    float bhh = 0.f, al = 0.f, om2 = 0.f, g2 = 0.f, vv = 0.f;
    float x = 0.f, y = 0.f, ec = 0.f;
    const float* ep = nullptr;
    float*       op = nullptr;
    if (tid < 256) {
        bhh = __ldg(&b_hh[dh]);
        al  = __ldg(&alpha[dh]);
        float om = __ldg(&omega[dh]);
        om2 = om * om;
        g2  = 2.f * __ldg(&gamma[dh]);
        vv  = __ldg(&vvec[dh]);
        int b = bg * 4 + (tid >> 6);
        ep = g_ext + (size_t)b * N_HID + dh;
        op = out   + (size_t)b * N_HID + dh;
        ec = __ldcg((float*)ep);                // ext for t=0
    }

    // dot-phase pointers
    const ulonglong2* wp = ((const ulonglong2*)smem) + (kh * 16) * 64 + hl;

    for (int t = 0; t < T_STEPS; ++t) {
        if (t > 0) {
            const uint32_t mb = ((t - 1) & 1) ? mbar1 : mbar0;
            mbar_wait_parity(mb, (unsigned)(((t - 1) >> 1) & 1));
            if (tid == 0) mbar_expect_tx(mb, TX_BYTES);   // re-arm for y_{t+1}

            // ---- dot: 4 rows x this thread's 64-k slice ----
            const ulonglong2* yb = ((const ulonglong2*)
                (smem + YS_F + ((t - 1) & 1) * 2048)) + kh * 16;
            unsigned long long a0[4], a1[4];
#pragma unroll
            for (int r = 0; r < 4; ++r) { a0[r] = 0ull; a1[r] = 0ull; }
#pragma unroll 8
            for (int j = 0; j < 16; ++j) {
                ulonglong2 wv = wp[j * 64];
#pragma unroll
                for (int r = 0; r < 4; ++r) {
                    ulonglong2 yv = yb[r * 128 + j];
                    asm("fma.rn.f32x2 %0, %1, %2, %0;" : "+l"(a0[r]) : "l"(yv.x), "l"(wv.x));
                    asm("fma.rn.f32x2 %0, %1, %2, %0;" : "+l"(a1[r]) : "l"(yv.y), "l"(wv.y));
                }
            }
#pragma unroll
            for (int r = 0; r < 4; ++r) {
                float2 f0 = *(float2*)&a0[r];
                float2 f1 = *(float2*)&a1[r];
                smem[RED_F + kh * 256 + r * 64 + hl] =
                    (f0.x + f0.y) + (f1.x + f1.y);
            }
        }
        __syncthreads();

        // ---- dynamics (threads 0-255) ----
        if (tid < 256) {
            float acc = 0.f;
            if (t > 0) {
#pragma unroll
                for (int k = 0; k < 8; ++k)
                    acc += smem[RED_F + k * 256 + tid];
            }
            float inp = ec + GAIN_REC * (acc + bhh + vv * x);
            float yn  = fmaf(DT_H, al * tanhf(inp) - om2 * x - g2 * y, y);
            float xn  = fmaf(DT_H, yn, x);
            x = xn; y = yn;
            smem[STAG_F + tid] = yn;
            op[(size_t)t * YN] = xn;
            ec = __ldcg((float*)(ep + (size_t)((t + 1) & (T_STEPS - 1)) * YN));
        }
        __syncthreads();

        // ---- broadcast yn to all 8 ranks via st.async (all 512 threads) ----
        {
            int r  = tid >> 6;                  // target rank
            int c  = tid & 63;                  // f4 chunk: row = c>>4, quad = c&15
            uint4 val = *(const uint4*)&smem[STAG_F + c * 4];
            uint32_t dstLocal = smem_u32 +
                (uint32_t)((YS_F + (t & 1) * 2048
                            + (c >> 4) * 512 + rank * 64 + (c & 15) * 4) * 4);
            const uint32_t mb = (t & 1) ? mbar1 : mbar0;
            st_async_v4(dstLocal, mb, (uint32_t)r, val);
        }
        // no fence, no arrive, no extra barrier — tx counting does it all
    }

    // drain final phase (y_1023 txs into my smem) before exit
    mbar_wait_parity(mbar1, (unsigned)((1023 >> 1) & 1));
    asm volatile("barrier.cluster.arrive.aligned;" ::: "memory");
    asm volatile("barrier.cluster.wait.aligned;"   ::: "memory");
}

// ---------------------------------------------------------------------------
// Launch
// ---------------------------------------------------------------------------
extern "C" void kernel_launch(void* const* d_in, const int* in_sizes, int n_in,
                              void* d_out, int out_size)
{
    const float* inputs = (const float*)d_in[0];
    const float* W_ih   = (const float*)d_in[1];
    const float* b_ih   = (const float*)d_in[2];
    const float* W_hh   = (const float*)d_in[3];
    const float* b_hh   = (const float*)d_in[4];
    const float* alpha  = (const float*)d_in[5];
    const float* omega  = (const float*)d_in[6];
    const float* gamma  = (const float*)d_in[7];
    const float* v      = (const float*)d_in[8];
    float* out = (float*)d_out;

    (void)in_sizes; (void)n_in; (void)out_size;

    cudaFuncSetAttribute(horn_rec4,
                         cudaFuncAttributeMaxDynamicSharedMemorySize,
                         SMEM_R_BYTES);

    dim3 gA(N_HID / TA_N, M_TOTAL / TA_M);
    ext_gemm_kernel<<<gA, 256>>>(inputs, W_ih, b_ih);

    horn_rec4<<<128, RNT, SMEM_R_BYTES>>>(W_hh, b_hh, alpha, omega,
                                          gamma, v, out);
}

// round 6
// speedup vs baseline: 1.8326x; 1.1304x over previous
#include <cuda_runtime.h>
#include <cuda_bf16.h>
#include <cstdint>

// ---------------------------------------------------------------------------
// Problem constants
// ---------------------------------------------------------------------------
#define T_STEPS   1024
#define BATCH     64
#define N_IN      256
#define N_HID     512
#define M_TOTAL   (T_STEPS * BATCH)       // 65536
#define YN        (BATCH * N_HID)         // 32768

#define GAIN_REC  0.04419417382415922f    // 1/sqrt(512)
#define DT_H      0.1f

__device__ float g_ext[(size_t)M_TOTAL * N_HID];   // inputs @ W_ih + b_ih

// ---------------------------------------------------------------------------
// Kernel A: ext = inputs @ W_ih + b_ih   (unchanged; ~0.45ms)
// ---------------------------------------------------------------------------
#define TA_M 64
#define TA_N 64
#define TA_K 32

__global__ __launch_bounds__(256) void ext_gemm_kernel(
    const float* __restrict__ A, const float* __restrict__ W,
    const float* __restrict__ bias)
{
    __shared__ float As[TA_K][TA_M + 4];
    __shared__ float Bs[TA_K][TA_N];

    const int tid = threadIdx.x;
    const int tx  = tid & 15;
    const int ty  = tid >> 4;
    const int m0  = blockIdx.y * TA_M;
    const int n0  = blockIdx.x * TA_N;

    float acc[4][4];
#pragma unroll
    for (int i = 0; i < 4; ++i)
#pragma unroll
        for (int j = 0; j < 4; ++j) acc[i][j] = 0.f;

    for (int kt = 0; kt < N_IN; kt += TA_K) {
#pragma unroll
        for (int j = 0; j < 2; ++j) {
            int f  = tid + j * 256;
            int r  = f >> 3;
            int c4 = f & 7;
            float4 v = *(const float4*)&A[(size_t)(m0 + r) * N_IN + kt + c4 * 4];
            As[c4 * 4 + 0][r] = v.x;
            As[c4 * 4 + 1][r] = v.y;
            As[c4 * 4 + 2][r] = v.z;
            As[c4 * 4 + 3][r] = v.w;
        }
#pragma unroll
        for (int j = 0; j < 2; ++j) {
            int f  = tid + j * 256;
            int r  = f >> 4;
            int c4 = f & 15;
            *(float4*)&Bs[r][c4 * 4] =
                *(const float4*)&W[(size_t)(kt + r) * N_HID + n0 + c4 * 4];
        }
        __syncthreads();
#pragma unroll
        for (int k = 0; k < TA_K; ++k) {
            float a[4], bb[4];
            *(float4*)a  = *(const float4*)&As[k][ty * 4];
            *(float4*)bb = *(const float4*)&Bs[k][tx * 4];
#pragma unroll
            for (int i = 0; i < 4; ++i)
#pragma unroll
                for (int j = 0; j < 4; ++j)
                    acc[i][j] = fmaf(a[i], bb[j], acc[i][j]);
        }
        __syncthreads();
    }

    float4 bv = *(const float4*)&bias[n0 + tx * 4];
#pragma unroll
    for (int i = 0; i < 4; ++i) {
        int m = m0 + ty * 4 + i;
        float4 o;
        o.x = acc[i][0] + bv.x;
        o.y = acc[i][1] + bv.y;
        o.z = acc[i][2] + bv.z;
        o.w = acc[i][3] + bv.w;
        *(float4*)&g_ext[(size_t)m * N_HID + n0 + tx * 4] = o;
    }
}

// ---------------------------------------------------------------------------
// Kernel B: persistent recurrence, 16 clusters x 8 CTAs.
//   Per-source-rank tx-counting mbarriers: warp-pair kh waits only on rank
//   kh's 1KB slice. Warps 8-15: wait->dot->partial->bar.arrive, then race to
//   the next step's wait. Warps 0-7: +dyn +st.async broadcast.
// ---------------------------------------------------------------------------
#define RNT 512

// SMEM layout (float indices)
#define WS_F    0                      // W slice [k4][hl] float4: 32768 floats
#define YS_F    32768                  // 2 bufs x [row(4)][512 f]: 4096 floats
#define RED_F   36864                  // partials [kh(8)][row(4)][hl(64)]: 2048
#define STAG_F  38912                  // yn staging [row*64+hl]: 256 floats
#define MBAR_F  39168                  // 16 mbarriers (128 B)
#define SMEM_R_BYTES ((MBAR_F + 32) * 4)

#define TX_BYTES 1024u                 // per-source-rank: 4 rows x 64 h x 4 B

__device__ __forceinline__ void mbar_init(uint32_t a, uint32_t cnt) {
    asm volatile("mbarrier.init.shared.b64 [%0], %1;" :: "r"(a), "r"(cnt) : "memory");
}
__device__ __forceinline__ void mbar_expect_tx(uint32_t a, uint32_t bytes) {
    asm volatile("mbarrier.arrive.expect_tx.shared.b64 _, [%0], %1;"
                 :: "r"(a), "r"(bytes) : "memory");
}
__device__ __forceinline__ void mbar_wait_parity(uint32_t a, uint32_t par) {
    asm volatile("{\n\t.reg .pred P;\n\t"
                 "WL_%=:\n\t"
                 "mbarrier.try_wait.parity.acquire.cluster.shared::cta.b64 P, [%0], %1, 0x989680;\n\t"
                 "@P bra WD_%=;\n\t"
                 "bra WL_%=;\n\t"
                 "WD_%=:\n\t}"
                 :: "r"(a), "r"(par) : "memory");
}
// st.async 16B to remote rank's smem, tx-counting on remote mbarrier
__device__ __forceinline__ void st_async_v4(uint32_t dstLocal, uint32_t mbarLocal,
                                            uint32_t rank, uint4 v) {
    asm volatile("{\n\t.reg .b32 rd, rm;\n\t"
                 "mapa.shared::cluster.u32 rd, %0, %2;\n\t"
                 "mapa.shared::cluster.u32 rm, %1, %2;\n\t"
                 "st.async.shared::cluster.mbarrier::complete_tx::bytes.v4.b32 "
                 "[rd], {%3, %4, %5, %6}, [rm];\n\t}"
                 :: "r"(dstLocal), "r"(mbarLocal), "r"(rank),
                    "r"(v.x), "r"(v.y), "r"(v.z), "r"(v.w) : "memory");
}

__global__ void __cluster_dims__(8, 1, 1) __launch_bounds__(RNT, 1)
horn_rec5(const float* __restrict__ W_hh,
          const float* __restrict__ b_hh,
          const float* __restrict__ alpha,
          const float* __restrict__ omega,
          const float* __restrict__ gamma,
          const float* __restrict__ vvec,
          float* __restrict__ out)
{
    extern __shared__ float smem[];

    const int tid  = threadIdx.x;
    const int bg   = blockIdx.x >> 3;           // cluster id (16)
    const int rank = blockIdx.x & 7;            // h0 = rank*64
    const int h0   = rank * 64;
    const int kh   = tid >> 6;                  // k-slice = source rank 0..7
    const int hl   = tid & 63;                  // hidden column 0..63
    const int warp = tid >> 5;
    const uint32_t smem_u32 = (uint32_t)__cvta_generic_to_shared(smem);
    // mbar[r][p] at MBAR_F*4 + (r*2+p)*8
    const uint32_t mbar_base = smem_u32 + MBAR_F * 4;

    // ---- fill W slice: ws[k4*64 + col] float4 packs a k-quad ----
    for (int idx = tid; idx < 64 * N_HID; idx += RNT) {
        int k = idx >> 6;
        int l = idx & 63;
        smem[WS_F + (k >> 2) * 256 + l * 4 + (k & 3)] =
            W_hh[(size_t)k * N_HID + h0 + l];
    }

    if (tid < 16) {
        mbar_init(mbar_base + tid * 8, 1);
    }
    __syncthreads();
    if (tid < 16) {
        mbar_expect_tx(mbar_base + tid * 8, TX_BYTES);  // arm phases for y_0,y_1
    }
    __syncthreads();
    asm volatile("barrier.cluster.arrive.aligned;" ::: "memory");
    asm volatile("barrier.cluster.wait.aligned;"   ::: "memory");

    // ---- dynamics-thread state (tid < 256: row = tid>>6, h = h0 + tid&63) ----
    const int dh = h0 + (tid & 63);
    float om2 = 0.f, g2 = 0.f, vv = 0.f, bhh = 0.f, dtal = 0.f;
    float x = 0.f, lin = 0.f, base = 0.f, ec = 0.f;
    const float* ep = nullptr;
    float*       op = nullptr;
    if (tid < 256) {
        bhh = __ldg(&b_hh[dh]);
        dtal = DT_H * __ldg(&alpha[dh]);
        float om = __ldg(&omega[dh]);
        om2 = om * om;
        g2  = 2.f * __ldg(&gamma[dh]);
        vv  = __ldg(&vvec[dh]);
        int b = bg * 4 + (tid >> 6);
        ep = g_ext + (size_t)b * N_HID + dh;
        op = out   + (size_t)b * N_HID + dh;
        ec = __ldcg((float*)ep);                 // ext for t=0
        lin  = 0.f;                              // y + h*(-om2*x - g2*y) at x=y=0
        base = GAIN_REC * bhh;                   // GAIN*(bhh + vv*x) at x=0
    }

    // dot-phase pointers
    const ulonglong2* wp = ((const ulonglong2*)smem) + (kh * 16) * 64 + hl;

    for (int t = 0; t < T_STEPS; ++t) {
        if (t > 0) {
            const int p = (t - 1) & 1;
            const uint32_t mb = mbar_base + (kh * 2 + p) * 8;
            mbar_wait_parity(mb, (unsigned)(((t - 1) >> 1) & 1));
            if ((tid & 63) == 0) mbar_expect_tx(mb, TX_BYTES);  // re-arm

            // ---- dot: 4 rows x this thread's 64-k slice ----
            const ulonglong2* yb = ((const ulonglong2*)
                (smem + YS_F + p * 2048)) + kh * 16;
            unsigned long long a0[4], a1[4];
#pragma unroll
            for (int r = 0; r < 4; ++r) { a0[r] = 0ull; a1[r] = 0ull; }
#pragma unroll 8
            for (int j = 0; j < 16; ++j) {
                ulonglong2 wv = wp[j * 64];
#pragma unroll
                for (int r = 0; r < 4; ++r) {
                    ulonglong2 yv = yb[r * 128 + j];
                    asm("fma.rn.f32x2 %0, %1, %2, %0;" : "+l"(a0[r]) : "l"(yv.x), "l"(wv.x));
                    asm("fma.rn.f32x2 %0, %1, %2, %0;" : "+l"(a1[r]) : "l"(yv.y), "l"(wv.y));
                }
            }
#pragma unroll
            for (int r = 0; r < 4; ++r) {
                float2 f0 = *(float2*)&a0[r];
                float2 f1 = *(float2*)&a1[r];
                smem[RED_F + kh * 256 + r * 64 + hl] =
                    (f0.x + f0.y) + (f1.x + f1.y);
            }
        }

        if (warp >= 8) {
            // signal partials ready; immediately chase next step's data
            asm volatile("bar.arrive 0, %0;" :: "n"(RNT) : "memory");
            continue;
        }

        // ---- warps 0-7: consume partials, dynamics, broadcast ----
        asm volatile("bar.sync 0, %0;" :: "n"(RNT) : "memory");

        {
            float acc = 0.f;
            if (t > 0) {
#pragma unroll
                for (int k = 0; k < 8; ++k)
                    acc += smem[RED_F + k * 256 + tid];
            }
            float inp = ec + fmaf(GAIN_REC, acc, base);
            float th  = tanhf(inp);
            float yn  = fmaf(dtal, th, lin);
            float xn  = fmaf(DT_H, yn, x);
            smem[STAG_F + tid] = yn;
            op[(size_t)t * YN] = xn;
            // precompute for next step
            lin  = fmaf(DT_H, fmaf(-om2, xn, -g2 * yn), yn);
            base = GAIN_REC * fmaf(vv, xn, bhh);
            x = xn;
            ec = __ldcg((float*)(ep + (size_t)((t + 1) & (T_STEPS - 1)) * YN));
        }
        asm volatile("bar.sync 1, 256;" ::: "memory");

        // ---- broadcast yn: 256 threads x 2 chunks of 16B via st.async ----
        {
            const uint32_t mbl = mbar_base + (rank * 2 + (t & 1)) * 8;
#pragma unroll
            for (int j = 0; j < 2; ++j) {
                int q = tid + j * 256;          // 0..511
                int d = q >> 6;                 // dest rank
                int c = q & 63;                 // chunk: row = c>>4, quad = c&15
                uint4 val = *(const uint4*)&smem[STAG_F + c * 4];
                uint32_t dstLocal = smem_u32 +
                    (uint32_t)((YS_F + (t & 1) * 2048
                                + (c >> 4) * 512 + rank * 64 + (c & 15) * 4) * 4);
                st_async_v4(dstLocal, mbl, (uint32_t)d, val);
            }
        }
    }

    // drain final in-flight phase (y_1023 into mbar[kh][1], parity 1)
    mbar_wait_parity(mbar_base + (kh * 2 + 1) * 8, 1u);
    asm volatile("barrier.cluster.arrive.aligned;" ::: "memory");
    asm volatile("barrier.cluster.wait.aligned;"   ::: "memory");
}

// ---------------------------------------------------------------------------
// Launch
// ---------------------------------------------------------------------------
extern "C" void kernel_launch(void* const* d_in, const int* in_sizes, int n_in,
                              void* d_out, int out_size)
{
    const float* inputs = (const float*)d_in[0];
    const float* W_ih   = (const float*)d_in[1];
    const float* b_ih   = (const float*)d_in[2];
    const float* W_hh   = (const float*)d_in[3];
    const float* b_hh   = (const float*)d_in[4];
    const float* alpha  = (const float*)d_in[5];
    const float* omega  = (const float*)d_in[6];
    const float* gamma  = (const float*)d_in[7];
    const float* v      = (const float*)d_in[8];
    float* out = (float*)d_out;

    (void)in_sizes; (void)n_in; (void)out_size;

    cudaFuncSetAttribute(horn_rec5,
                         cudaFuncAttributeMaxDynamicSharedMemorySize,
                         SMEM_R_BYTES);

    dim3 gA(N_HID / TA_N, M_TOTAL / TA_M);
    ext_gemm_kernel<<<gA, 256>>>(inputs, W_ih, b_ih);

    horn_rec5<<<128, RNT, SMEM_R_BYTES>>>(W_hh, b_hh, alpha, omega,
                                          gamma, v, out);
}

// round 7
// speedup vs baseline: 1.8741x; 1.0227x over previous
#include <cuda_runtime.h>
#include <cuda_bf16.h>
#include <cstdint>

// ---------------------------------------------------------------------------
// Problem constants
// ---------------------------------------------------------------------------
#define T_STEPS   1024
#define BATCH     64
#define N_IN      256
#define N_HID     512
#define M_TOTAL   (T_STEPS * BATCH)       // 65536
#define YN        (BATCH * N_HID)         // 32768

#define GAIN_REC  0.04419417382415922f    // 1/sqrt(512)
#define DT_H      0.1f

__device__ float g_ext[(size_t)M_TOTAL * N_HID];   // inputs @ W_ih + b_ih

// ---------------------------------------------------------------------------
// Kernel A: ext = inputs @ W_ih + b_ih   (unchanged; ~0.45ms)
// ---------------------------------------------------------------------------
#define TA_M 64
#define TA_N 64
#define TA_K 32

__global__ __launch_bounds__(256) void ext_gemm_kernel(
    const float* __restrict__ A, const float* __restrict__ W,
    const float* __restrict__ bias)
{
    __shared__ float As[TA_K][TA_M + 4];
    __shared__ float Bs[TA_K][TA_N];

    const int tid = threadIdx.x;
    const int tx  = tid & 15;
    const int ty  = tid >> 4;
    const int m0  = blockIdx.y * TA_M;
    const int n0  = blockIdx.x * TA_N;

    float acc[4][4];
#pragma unroll
    for (int i = 0; i < 4; ++i)
#pragma unroll
        for (int j = 0; j < 4; ++j) acc[i][j] = 0.f;

    for (int kt = 0; kt < N_IN; kt += TA_K) {
#pragma unroll
        for (int j = 0; j < 2; ++j) {
            int f  = tid + j * 256;
            int r  = f >> 3;
            int c4 = f & 7;
            float4 v = *(const float4*)&A[(size_t)(m0 + r) * N_IN + kt + c4 * 4];
            As[c4 * 4 + 0][r] = v.x;
            As[c4 * 4 + 1][r] = v.y;
            As[c4 * 4 + 2][r] = v.z;
            As[c4 * 4 + 3][r] = v.w;
        }
#pragma unroll
        for (int j = 0; j < 2; ++j) {
            int f  = tid + j * 256;
            int r  = f >> 4;
            int c4 = f & 15;
            *(float4*)&Bs[r][c4 * 4] =
                *(const float4*)&W[(size_t)(kt + r) * N_HID + n0 + c4 * 4];
        }
        __syncthreads();
#pragma unroll
        for (int k = 0; k < TA_K; ++k) {
            float a[4], bb[4];
            *(float4*)a  = *(const float4*)&As[k][ty * 4];
            *(float4*)bb = *(const float4*)&Bs[k][tx * 4];
#pragma unroll
            for (int i = 0; i < 4; ++i)
#pragma unroll
                for (int j = 0; j < 4; ++j)
                    acc[i][j] = fmaf(a[i], bb[j], acc[i][j]);
        }
        __syncthreads();
    }

    float4 bv = *(const float4*)&bias[n0 + tx * 4];
#pragma unroll
    for (int i = 0; i < 4; ++i) {
        int m = m0 + ty * 4 + i;
        float4 o;
        o.x = acc[i][0] + bv.x;
        o.y = acc[i][1] + bv.y;
        o.z = acc[i][2] + bv.z;
        o.w = acc[i][3] + bv.w;
        *(float4*)&g_ext[(size_t)m * N_HID + n0 + tx * 4] = o;
    }
}

// ---------------------------------------------------------------------------
// Kernel B: persistent recurrence, 16 clusters x 8 CTAs, 768 threads.
//   Warps 0-15 : pure dot (wait kh-mbar -> dot -> partial -> bar.arrive).
//   Warps 16-23: pure dyn/comm (bar.sync -> reduce -> dyn -> st.async bcast).
//   RED partials double-buffered by step parity; per-source-rank mbarriers.
// ---------------------------------------------------------------------------
#define RNT 768

// SMEM layout (float indices)
#define WS_F    0                      // W slice [k4][hl] float4: 32768 floats
#define YS_F    32768                  // 2 bufs x [row(4)][512 f]: 4096 floats
#define RED_F   36864                  // 2 bufs x [kh(8)][row(4)][hl(64)]: 4096
#define STAG_F  40960                  // yn staging [row*64+hl]: 256 floats
#define MBAR_F  41216                  // 16 mbarriers (128 B)
#define SMEM_R_BYTES ((MBAR_F + 32) * 4)

#define TX_BYTES 1024u                 // per-source-rank: 4 rows x 64 h x 4 B

__device__ __forceinline__ void mbar_init(uint32_t a, uint32_t cnt) {
    asm volatile("mbarrier.init.shared.b64 [%0], %1;" :: "r"(a), "r"(cnt) : "memory");
}
__device__ __forceinline__ void mbar_expect_tx(uint32_t a, uint32_t bytes) {
    asm volatile("mbarrier.arrive.expect_tx.shared.b64 _, [%0], %1;"
                 :: "r"(a), "r"(bytes) : "memory");
}
__device__ __forceinline__ void mbar_wait_parity(uint32_t a, uint32_t par) {
    asm volatile("{\n\t.reg .pred P;\n\t"
                 "WL_%=:\n\t"
                 "mbarrier.try_wait.parity.acquire.cluster.shared::cta.b64 P, [%0], %1, 0x989680;\n\t"
                 "@P bra WD_%=;\n\t"
                 "bra WL_%=;\n\t"
                 "WD_%=:\n\t}"
                 :: "r"(a), "r"(par) : "memory");
}
__device__ __forceinline__ void st_async_v4(uint32_t dstLocal, uint32_t mbarLocal,
                                            uint32_t rank, uint4 v) {
    asm volatile("{\n\t.reg .b32 rd, rm;\n\t"
                 "mapa.shared::cluster.u32 rd, %0, %2;\n\t"
                 "mapa.shared::cluster.u32 rm, %1, %2;\n\t"
                 "st.async.shared::cluster.mbarrier::complete_tx::bytes.v4.b32 "
                 "[rd], {%3, %4, %5, %6}, [rm];\n\t}"
                 :: "r"(dstLocal), "r"(mbarLocal), "r"(rank),
                    "r"(v.x), "r"(v.y), "r"(v.z), "r"(v.w) : "memory");
}
__device__ __forceinline__ float tanh_approx(float x) {
    float r;
    asm("tanh.approx.f32 %0, %1;" : "=f"(r) : "f"(x));
    return r;
}

__global__ void __cluster_dims__(8, 1, 1) __launch_bounds__(RNT, 1)
horn_rec6(const float* __restrict__ W_hh,
          const float* __restrict__ b_hh,
          const float* __restrict__ alpha,
          const float* __restrict__ omega,
          const float* __restrict__ gamma,
          const float* __restrict__ vvec,
          float* __restrict__ out)
{
    extern __shared__ float smem[];

    const int tid  = threadIdx.x;
    const int bg   = blockIdx.x >> 3;           // cluster id (16)
    const int rank = blockIdx.x & 7;            // h0 = rank*64
    const int h0   = rank * 64;
    const int warp = tid >> 5;
    const uint32_t smem_u32 = (uint32_t)__cvta_generic_to_shared(smem);
    const uint32_t mbar_base = smem_u32 + MBAR_F * 4;   // mbar[r][p] stride 8B

    // ---- fill W slice: ws[k4*64 + col] float4 packs a k-quad ----
    for (int idx = tid; idx < 64 * N_HID; idx += RNT) {
        int k = idx >> 6;
        int l = idx & 63;
        smem[WS_F + (k >> 2) * 256 + l * 4 + (k & 3)] =
            W_hh[(size_t)k * N_HID + h0 + l];
    }

    if (tid < 16) mbar_init(mbar_base + tid * 8, 1);
    __syncthreads();
    if (tid < 16) mbar_expect_tx(mbar_base + tid * 8, TX_BYTES);
    __syncthreads();
    asm volatile("barrier.cluster.arrive.aligned;" ::: "memory");
    asm volatile("barrier.cluster.wait.aligned;"   ::: "memory");

    if (warp < 16) {
        // =================== DOT WARPS (tid 0..511) ===================
        const int kh = tid >> 6;                // k-slice = source rank
        const int hl = tid & 63;
        const ulonglong2* wp = ((const ulonglong2*)smem) + (kh * 16) * 64 + hl;
        float* red0 = smem + RED_F + kh * 256 + hl;

        for (int t = 0; t < T_STEPS; ++t) {
            if (t > 0) {
                const int p = (t - 1) & 1;
                const uint32_t mb = mbar_base + (kh * 2 + p) * 8;
                mbar_wait_parity(mb, (unsigned)(((t - 1) >> 1) & 1));
                if ((tid & 63) == 0) mbar_expect_tx(mb, TX_BYTES);

                const ulonglong2* yb = ((const ulonglong2*)
                    (smem + YS_F + p * 2048)) + kh * 16;
                unsigned long long a0[4], a1[4];
#pragma unroll
                for (int r = 0; r < 4; ++r) { a0[r] = 0ull; a1[r] = 0ull; }
#pragma unroll
                for (int j = 0; j < 16; ++j) {
                    ulonglong2 wv = wp[j * 64];
#pragma unroll
                    for (int r = 0; r < 4; ++r) {
                        ulonglong2 yv = yb[r * 128 + j];
                        asm("fma.rn.f32x2 %0, %1, %2, %0;" : "+l"(a0[r]) : "l"(yv.x), "l"(wv.x));
                        asm("fma.rn.f32x2 %0, %1, %2, %0;" : "+l"(a1[r]) : "l"(yv.y), "l"(wv.y));
                    }
                }
                float* rp = red0 + (t & 1) * 2048;
#pragma unroll
                for (int r = 0; r < 4; ++r) {
                    float2 f0 = *(float2*)&a0[r];
                    float2 f1 = *(float2*)&a1[r];
                    rp[r * 64] = (f0.x + f0.y) + (f1.x + f1.y);
                }
            }
            asm volatile("bar.arrive 0, %0;" :: "n"(RNT) : "memory");
        }
        // drain final in-flight phase (y_1023 into mbar[kh][1], parity 1)
        mbar_wait_parity(mbar_base + (kh * 2 + 1) * 8, 1u);
    } else {
        // =================== DYN/COMM WARPS (tid 512..767) ===================
        const int tid2 = tid - 512;             // 0..255
        const int row  = tid2 >> 6;
        const int hl   = tid2 & 63;
        const int dh   = h0 + hl;

        const float bhh  = __ldg(&b_hh[dh]);
        const float dtal = DT_H * __ldg(&alpha[dh]);
        const float om   = __ldg(&omega[dh]);
        const float om2  = om * om;
        const float g2   = 2.f * __ldg(&gamma[dh]);
        const float vv   = __ldg(&vvec[dh]);
        const int b = bg * 4 + row;
        const float* ep = g_ext + (size_t)b * N_HID + dh;
        float*       op = out   + (size_t)b * N_HID + dh;

        float x = 0.f;
        float lin  = 0.f;                       // y + h*(-om2*x - g2*y)
        float base = GAIN_REC * bhh;            // GAIN*(bhh + vv*x)
        float ec = __ldcg((float*)ep);          // ext t
        float e1 = __ldcg((float*)(ep + YN));   // ext t+1

        for (int t = 0; t < T_STEPS; ++t) {
            asm volatile("bar.sync 0, %0;" :: "n"(RNT) : "memory");

            float acc = 0.f;
            if (t > 0) {
                const float* rp = smem + RED_F + (t & 1) * 2048 + tid2;
#pragma unroll
                for (int k = 0; k < 8; ++k)
                    acc += rp[k * 256];
            }
            float inp = ec + fmaf(GAIN_REC, acc, base);
            float th  = tanh_approx(inp);
            float yn  = fmaf(dtal, th, lin);
            float xn  = fmaf(DT_H, yn, x);
            smem[STAG_F + tid2] = yn;
            op[(size_t)t * YN] = xn;
            lin  = fmaf(DT_H, fmaf(-om2, xn, -g2 * yn), yn);
            base = GAIN_REC * fmaf(vv, xn, bhh);
            x = xn;
            ec = e1;
            e1 = __ldcg((float*)(ep + (size_t)((t + 2) & (T_STEPS - 1)) * YN));

            asm volatile("bar.sync 1, 256;" ::: "memory");

            // broadcast yn: 256 threads x 2 x 16B st.async
            const uint32_t mbl = mbar_base + (rank * 2 + (t & 1)) * 8;
#pragma unroll
            for (int j = 0; j < 2; ++j) {
                int q = tid2 + j * 256;         // 0..511
                int d = q >> 6;                 // dest rank
                int c = q & 63;                 // chunk: row=c>>4, quad=c&15
                uint4 val = *(const uint4*)&smem[STAG_F + c * 4];
                uint32_t dstLocal = smem_u32 +
                    (uint32_t)((YS_F + (t & 1) * 2048
                                + (c >> 4) * 512 + rank * 64 + (c & 15) * 4) * 4);
                st_async_v4(dstLocal, mbl, (uint32_t)d, val);
            }
        }
    }

    asm volatile("barrier.cluster.arrive.aligned;" ::: "memory");
    asm volatile("barrier.cluster.wait.aligned;"   ::: "memory");
}

// ---------------------------------------------------------------------------
// Launch
// ---------------------------------------------------------------------------
extern "C" void kernel_launch(void* const* d_in, const int* in_sizes, int n_in,
                              void* d_out, int out_size)
{
    const float* inputs = (const float*)d_in[0];
    const float* W_ih   = (const float*)d_in[1];
    const float* b_ih   = (const float*)d_in[2];
    const float* W_hh   = (const float*)d_in[3];
    const float* b_hh   = (const float*)d_in[4];
    const float* alpha  = (const float*)d_in[5];
    const float* omega  = (const float*)d_in[6];
    const float* gamma  = (const float*)d_in[7];
    const float* v      = (const float*)d_in[8];
    float* out = (float*)d_out;

    (void)in_sizes; (void)n_in; (void)out_size;

    cudaFuncSetAttribute(horn_rec6,
                         cudaFuncAttributeMaxDynamicSharedMemorySize,
                         SMEM_R_BYTES);

    dim3 gA(N_HID / TA_N, M_TOTAL / TA_M);
    ext_gemm_kernel<<<gA, 256>>>(inputs, W_ih, b_ih);

    horn_rec6<<<128, RNT, SMEM_R_BYTES>>>(W_hh, b_hh, alpha, omega,
                                          gamma, v, out);
}